// round 1
// baseline (speedup 1.0000x reference)
#include <cuda_runtime.h>
#include <cuda_bf16.h>
#include <cstdint>

// Problem constants (shape-specialized; sizes re-derived at launch where cheap)
#define OUTP 64
#define MIDP 8
#define NSAMP 32
#define TR 128            // rows per block == threads per block in main kernel
#define SEG_CAP 131072    // max sets supported by static scratch (actual: 50000)

// ---------- device scratch (no allocations allowed) ----------
__device__ double g_mom[5];                       // Sx, Sy, Sxx, Syy, Sxy
__device__ float  g_params[40];                   // BN affine, A[8][2], cq[8], bv[8]
__device__ unsigned long long g_wpack[OUTP * MIDP]; // packed {wq, wv} c-major
__device__ float  g_seg[SEG_CAP * 16];            // per-set: [0:8)=sum e, [8:16)=sum v*e

// ---------- helpers ----------
__device__ __forceinline__ unsigned long long pack2(float lo, float hi) {
    unsigned long long r;
    asm("mov.b64 %0, {%1, %2};" : "=l"(r) : "r"(__float_as_uint(lo)), "r"(__float_as_uint(hi)));
    return r;
}
__device__ __forceinline__ void unpack2(unsigned long long p, float& lo, float& hi) {
    unsigned a, b;
    asm("mov.b64 {%0, %1}, %2;" : "=r"(a), "=r"(b) : "l"(p));
    lo = __uint_as_float(a); hi = __uint_as_float(b);
}
__device__ __forceinline__ void ffma2(unsigned long long& acc, unsigned long long a, unsigned long long b) {
    asm("fma.rn.f32x2 %0, %1, %2, %0;" : "+l"(acc) : "l"(a), "l"(b));
}

// ---------- kernel 1: translation 2nd-order moments ----------
__global__ void k_moments(const float2* __restrict__ tr, int n) {
    int i0 = blockIdx.x * blockDim.x + threadIdx.x;
    int stride = gridDim.x * blockDim.x;
    float sx = 0.f, sy = 0.f, sxx = 0.f, syy = 0.f, sxy = 0.f;
    for (int i = i0; i < n; i += stride) {
        float2 v = tr[i];
        sx += v.x; sy += v.y;
        sxx += v.x * v.x; syy += v.y * v.y; sxy += v.x * v.y;
    }
    // warp reduce
    #pragma unroll
    for (int o = 16; o; o >>= 1) {
        sx  += __shfl_down_sync(0xffffffffu, sx,  o);
        sy  += __shfl_down_sync(0xffffffffu, sy,  o);
        sxx += __shfl_down_sync(0xffffffffu, sxx, o);
        syy += __shfl_down_sync(0xffffffffu, syy, o);
        sxy += __shfl_down_sync(0xffffffffu, sxy, o);
    }
    __shared__ float red[5][8];
    int lane = threadIdx.x & 31, wid = threadIdx.x >> 5;
    if (lane == 0) { red[0][wid] = sx; red[1][wid] = sy; red[2][wid] = sxx; red[3][wid] = syy; red[4][wid] = sxy; }
    __syncthreads();
    if (wid == 0) {
        int nw = blockDim.x >> 5;
        float v = (lane < nw && lane < 8) ? red[0][lane] : 0.f;
        float v1 = (lane < nw && lane < 8) ? red[1][lane] : 0.f;
        float v2 = (lane < nw && lane < 8) ? red[2][lane] : 0.f;
        float v3 = (lane < nw && lane < 8) ? red[3][lane] : 0.f;
        float v4 = (lane < nw && lane < 8) ? red[4][lane] : 0.f;
        #pragma unroll
        for (int o = 4; o; o >>= 1) {
            v  += __shfl_down_sync(0xffffffffu, v,  o);
            v1 += __shfl_down_sync(0xffffffffu, v1, o);
            v2 += __shfl_down_sync(0xffffffffu, v2, o);
            v3 += __shfl_down_sync(0xffffffffu, v3, o);
            v4 += __shfl_down_sync(0xffffffffu, v4, o);
        }
        if (lane == 0) {
            atomicAdd(&g_mom[0], (double)v);
            atomicAdd(&g_mom[1], (double)v1);
            atomicAdd(&g_mom[2], (double)v2);
            atomicAdd(&g_mom[3], (double)v3);
            atomicAdd(&g_mom[4], (double)v4);
        }
    }
}

// ---------- kernel 2: fold BN + linear layers into small param set ----------
__global__ void k_params(const float* __restrict__ Wq, const float* __restrict__ bq,
                         const float* __restrict__ Wv, const float* __restrict__ bv,
                         const float* __restrict__ Wp1, const float* __restrict__ gma,
                         const float* __restrict__ bet, const float* __restrict__ Wp2,
                         const float* __restrict__ bp2, double inv_n) {
    int t = threadIdx.x;
    // packed weights {wq[j][c], wv[j][c]}, c-major
    for (int i = t; i < OUTP * MIDP; i += blockDim.x) {
        int c = i >> 3, j = i & 7;
        g_wpack[i] = pack2(Wq[j * OUTP + c], Wv[j * OUTP + c]);
    }
    if (t == 0) {
        double mx = g_mom[0] * inv_n, my = g_mom[1] * inv_n;
        double vxx = g_mom[2] * inv_n - mx * mx;
        double vyy = g_mom[3] * inv_n - my * my;
        double vxy = g_mom[4] * inv_n - mx * my;
        for (int j = 0; j < 2; ++j) {
            double w0 = (double)Wp1[j * 2], w1 = (double)Wp1[j * 2 + 1];
            double mean = w0 * mx + w1 * my;
            double var  = w0 * w0 * vxx + 2.0 * w0 * w1 * vxy + w1 * w1 * vyy;
            double sc   = (double)gma[j] / sqrt(var + 1e-5);
            g_params[j * 3 + 0] = (float)(w0 * sc);
            g_params[j * 3 + 1] = (float)(w1 * sc);
            g_params[j * 3 + 2] = (float)((double)bet[j] - mean * sc);
        }
    }
    if (t < MIDP) {
        int j = t;
        float a0 = 0.f, a1 = 0.f, cq = 0.f;
        for (int c = 0; c < OUTP; ++c) {
            float w = Wq[j * OUTP + c];
            a0 += w * Wp2[c * 2];
            a1 += w * Wp2[c * 2 + 1];
            cq += w * bp2[c];
        }
        g_params[6 + 2 * j] = a0;
        g_params[7 + 2 * j] = a1;
        g_params[22 + j]    = cq + bq[j];
        g_params[30 + j]    = bv[j];
    }
}

// ---------- kernel 3: main fused pass ----------
// 128 threads, 128 rows per block. Reads outputs once; produces:
//   d_out <- features (per-set sum over NS rows)
//   g_seg <- atomically accumulated sum(e) and sum(v*e) per set index
__global__ __launch_bounds__(TR) void k_main(const float* __restrict__ outputs,
                                             const float* __restrict__ translation,
                                             const int* __restrict__ indexes,
                                             float* __restrict__ out,
                                             int n_rows, int n_sets) {
    __shared__ float xs[OUTP * (TR + 1)];          // transposed: xs[c*(TR+1)+r]
    __shared__ unsigned long long wsh[OUTP * MIDP];
    __shared__ float psh[40];

    const int t = threadIdx.x;
    const int row0 = blockIdx.x * TR;

    if (t < 40) psh[t] = g_params[t];
    for (int i = t; i < OUTP * MIDP; i += TR) wsh[i] = g_wpack[i];

    // coalesced stage into transposed shared tile (stride TR+1 -> conflict-free)
    {
        const float* gx = outputs + (size_t)row0 * OUTP;
        #pragma unroll
        for (int it = 0; it < OUTP; ++it) {
            int idx = it * TR + t;           // linear within tile, coalesced in gmem
            int r = idx >> 6;                // /OUTP
            int c = idx & (OUTP - 1);
            float v = (row0 + r < n_rows) ? gx[idx] : 0.f;
            xs[c * (TR + 1) + r] = v;
        }
    }
    __syncthreads();

    // per-row fused {q, v} GEMV via packed f32x2 FMA
    unsigned long long acc[MIDP];
    #pragma unroll
    for (int j = 0; j < MIDP; ++j) acc[j] = 0ull;

    #pragma unroll 16
    for (int c = 0; c < OUTP; ++c) {
        float x = xs[c * (TR + 1) + t];
        unsigned long long xp = pack2(x, x);
        const unsigned long long* wr = &wsh[c * MIDP];
        #pragma unroll
        for (int j = 0; j < MIDP; ++j) ffma2(acc[j], xp, wr[j]);
    }

    // epilogue: positional correction, exp, scatter-add
    const int row = row0 + t;
    if (row < n_rows) {
        float2 trv = ((const float2*)translation)[row];
        float r0 = fmaxf(psh[0] * trv.x + psh[1] * trv.y + psh[2], 0.f);
        float r1 = fmaxf(psh[3] * trv.x + psh[4] * trv.y + psh[5], 0.f);
        int sidx = indexes[row];
        float* seg = g_seg + (size_t)sidx * 16;
        #pragma unroll
        for (int j = 0; j < MIDP; ++j) {
            float q, v;
            unpack2(acc[j], q, v);
            q += psh[6 + 2 * j] * r0 + psh[7 + 2 * j] * r1 + psh[22 + j];
            v += psh[30 + j];
            float e = __expf(q);
            atomicAdd(seg + j, e);
            atomicAdd(seg + 8 + j, v * e);
        }
    }

    // features: 4 complete sets per block, from the shared tile (no atomics)
    {
        int ls = t >> 5;            // local set 0..3
        int c0 = t & 31;
        int sg = row0 / NSAMP + ls; // global set
        if (sg < n_sets) {
            #pragma unroll
            for (int half = 0; half < 2; ++half) {
                int c = c0 + half * 32;
                float s = 0.f;
                #pragma unroll
                for (int r = 0; r < NSAMP; ++r) s += xs[c * (TR + 1) + ls * NSAMP + r];
                out[(size_t)sg * OUTP + c] = s;
            }
        }
    }
}

// ---------- kernel 4: finalize ----------
__global__ void k_final(float* __restrict__ out, int total) {
    int i = blockIdx.x * blockDim.x + threadIdx.x;
    if (i < total) {
        int s = i >> 6;          // / OUTP
        int c = i & 63;
        int j = c & 7;
        float gs = g_seg[(size_t)s * 16 + j];
        float sv = g_seg[(size_t)s * 16 + 8 + j];
        float res = (gs > 0.f) ? (sv / gs) : 0.f;
        out[i] += res;
    }
}

// ---------- launcher ----------
extern "C" void kernel_launch(void* const* d_in, const int* in_sizes, int n_in,
                              void* d_out, int out_size) {
    const float* outputs     = (const float*)d_in[0];
    const float* translation = (const float*)d_in[1];
    const int*   indexes     = (const int*)d_in[2];
    const float* Wq  = (const float*)d_in[3];
    const float* bq  = (const float*)d_in[4];
    const float* Wv  = (const float*)d_in[5];
    const float* bv  = (const float*)d_in[6];
    const float* Wp1 = (const float*)d_in[7];
    const float* gma = (const float*)d_in[8];
    const float* bet = (const float*)d_in[9];
    const float* Wp2 = (const float*)d_in[10];
    const float* bp2 = (const float*)d_in[11];

    int n_rows = in_sizes[2];                 // N = SIZE * NS
    int n_sets = out_size / OUTP;             // SIZE
    if (n_sets > SEG_CAP) n_sets = SEG_CAP;   // static scratch bound

    void* segp = nullptr; void* momp = nullptr;
    cudaGetSymbolAddress(&segp, g_seg);
    cudaGetSymbolAddress(&momp, g_mom);
    cudaMemsetAsync(segp, 0, (size_t)n_sets * 16 * sizeof(float));
    cudaMemsetAsync(momp, 0, 5 * sizeof(double));

    k_moments<<<1024, 256>>>((const float2*)translation, n_rows);
    k_params<<<1, 128>>>(Wq, bq, Wv, bv, Wp1, gma, bet, Wp2, bp2, 1.0 / (double)n_rows);
    int nblocks = (n_rows + TR - 1) / TR;
    k_main<<<nblocks, TR>>>(outputs, translation, indexes, (float*)d_out, n_rows, n_sets);
    k_final<<<(out_size + 255) / 256, 256>>>((float*)d_out, out_size);
}

// round 3
// speedup vs baseline: 1.6723x; 1.6723x over previous
#include <cuda_runtime.h>
#include <cuda_bf16.h>
#include <cstdint>

#define OUTP 64
#define MIDP 8
#define BT 128            // threads per block (k_main)
#define BR 256            // rows per block
#define CH 32             // columns per phase (2 phases cover OUTP=64)
#define XSTRIDE 257       // padded row stride in shared tile (odd -> conflict-free)
#define SEG_CAP 131072

// ---------- device scratch ----------
__device__ double g_mom[5];
__device__ float  g_params[40];
__device__ unsigned long long g_wpack[OUTP * MIDP];     // packed {wq,wv}, c-major
__device__ __align__(16) float g_seg[SEG_CAP * 16];     // [0:8)=sum e, [8:16)=sum v*e

// ---------- helpers ----------
__device__ __forceinline__ unsigned long long pack2(float lo, float hi) {
    unsigned long long r;
    asm("mov.b64 %0, {%1, %2};" : "=l"(r) : "r"(__float_as_uint(lo)), "r"(__float_as_uint(hi)));
    return r;
}
__device__ __forceinline__ void unpack2(unsigned long long p, float& lo, float& hi) {
    unsigned a, b;
    asm("mov.b64 {%0, %1}, %2;" : "=r"(a), "=r"(b) : "l"(p));
    lo = __uint_as_float(a); hi = __uint_as_float(b);
}
__device__ __forceinline__ void ffma2(unsigned long long& acc, unsigned long long a, unsigned long long b) {
    asm("fma.rn.f32x2 %0, %1, %2, %0;" : "+l"(acc) : "l"(a), "l"(b));
}
__device__ __forceinline__ void red4(float* p, float a, float b, float c, float d) {
    asm volatile("red.global.add.v4.f32 [%0], {%1, %2, %3, %4};"
                 :: "l"(p), "f"(a), "f"(b), "f"(c), "f"(d) : "memory");
}

// ---------- kernel 1: translation 2nd-order moments ----------
__global__ void k_moments(const float2* __restrict__ tr, int n) {
    int i0 = blockIdx.x * blockDim.x + threadIdx.x;
    int stride = gridDim.x * blockDim.x;
    float sx = 0.f, sy = 0.f, sxx = 0.f, syy = 0.f, sxy = 0.f;
    for (int i = i0; i < n; i += stride) {
        float2 v = tr[i];
        sx += v.x; sy += v.y;
        sxx += v.x * v.x; syy += v.y * v.y; sxy += v.x * v.y;
    }
    #pragma unroll
    for (int o = 16; o; o >>= 1) {
        sx  += __shfl_down_sync(0xffffffffu, sx,  o);
        sy  += __shfl_down_sync(0xffffffffu, sy,  o);
        sxx += __shfl_down_sync(0xffffffffu, sxx, o);
        syy += __shfl_down_sync(0xffffffffu, syy, o);
        sxy += __shfl_down_sync(0xffffffffu, sxy, o);
    }
    __shared__ float red[5][8];
    int lane = threadIdx.x & 31, wid = threadIdx.x >> 5;
    if (lane == 0) { red[0][wid] = sx; red[1][wid] = sy; red[2][wid] = sxx; red[3][wid] = syy; red[4][wid] = sxy; }
    __syncthreads();
    if (wid == 0) {
        int nw = blockDim.x >> 5;
        float v0 = (lane < nw && lane < 8) ? red[0][lane] : 0.f;
        float v1 = (lane < nw && lane < 8) ? red[1][lane] : 0.f;
        float v2 = (lane < nw && lane < 8) ? red[2][lane] : 0.f;
        float v3 = (lane < nw && lane < 8) ? red[3][lane] : 0.f;
        float v4 = (lane < nw && lane < 8) ? red[4][lane] : 0.f;
        #pragma unroll
        for (int o = 4; o; o >>= 1) {
            v0 += __shfl_down_sync(0xffffffffu, v0, o);
            v1 += __shfl_down_sync(0xffffffffu, v1, o);
            v2 += __shfl_down_sync(0xffffffffu, v2, o);
            v3 += __shfl_down_sync(0xffffffffu, v3, o);
            v4 += __shfl_down_sync(0xffffffffu, v4, o);
        }
        if (lane == 0) {
            atomicAdd(&g_mom[0], (double)v0);
            atomicAdd(&g_mom[1], (double)v1);
            atomicAdd(&g_mom[2], (double)v2);
            atomicAdd(&g_mom[3], (double)v3);
            atomicAdd(&g_mom[4], (double)v4);
        }
    }
}

// ---------- kernel 2: fold all small layers into params ----------
__global__ void k_params(const float* __restrict__ Wq, const float* __restrict__ bq,
                         const float* __restrict__ Wv, const float* __restrict__ bv,
                         const float* __restrict__ Wp1, const float* __restrict__ gma,
                         const float* __restrict__ bet, const float* __restrict__ Wp2,
                         const float* __restrict__ bp2, double inv_n) {
    int t = threadIdx.x;
    for (int i = t; i < OUTP * MIDP; i += blockDim.x) {
        int c = i >> 3, j = i & 7;
        g_wpack[i] = pack2(Wq[j * OUTP + c], Wv[j * OUTP + c]);
    }
    if (t == 0) {
        double mx = g_mom[0] * inv_n, my = g_mom[1] * inv_n;
        double vxx = g_mom[2] * inv_n - mx * mx;
        double vyy = g_mom[3] * inv_n - my * my;
        double vxy = g_mom[4] * inv_n - mx * my;
        for (int j = 0; j < 2; ++j) {
            double w0 = (double)Wp1[j * 2], w1 = (double)Wp1[j * 2 + 1];
            double mean = w0 * mx + w1 * my;
            double var  = w0 * w0 * vxx + 2.0 * w0 * w1 * vxy + w1 * w1 * vyy;
            double sc   = (double)gma[j] / sqrt(var + 1e-5);
            g_params[j * 3 + 0] = (float)(w0 * sc);
            g_params[j * 3 + 1] = (float)(w1 * sc);
            g_params[j * 3 + 2] = (float)((double)bet[j] - mean * sc);
        }
    }
    if (t < MIDP) {
        int j = t;
        float a0 = 0.f, a1 = 0.f, cq = 0.f;
        for (int c = 0; c < OUTP; ++c) {
            float w = Wq[j * OUTP + c];
            a0 += w * Wp2[c * 2];
            a1 += w * Wp2[c * 2 + 1];
            cq += w * bp2[c];
        }
        g_params[6 + 2 * j] = a0;
        g_params[7 + 2 * j] = a1;
        g_params[22 + j]    = cq + bq[j];
        g_params[30 + j]    = bv[j];
    }
}

// ---------- kernel 3: main fused pass ----------
// 128 threads process 256 rows (2 rows/thread), columns in 2 phases of 32.
// Weight loads amortized over 2 rows and vectorized (LDS.128).
// Features accumulated in registers during staging (fixed column per thread).
__global__ __launch_bounds__(BT, 4) void k_main(const float* __restrict__ outputs,
                                                const float2* __restrict__ translation,
                                                const int* __restrict__ indexes,
                                                float* __restrict__ out,
                                                int n_rows) {
    __shared__ float xs[CH * XSTRIDE];                 // xs[c][r], r in [0,256)
    __shared__ unsigned long long wsh[OUTP * MIDP];
    __shared__ float psh[40];
    __shared__ float fsh[4 * 8 * 32];                  // [rgrp][set][col]

    const int t = threadIdx.x;
    const int row0 = blockIdx.x * BR;
    const int c = t & 31;            // fixed column (within phase) for staging
    const int rgrp = t >> 5;         // row-parity group 0..3

    if (t < 40) psh[t] = g_params[t];
    #pragma unroll
    for (int i = 0; i < 4; ++i) wsh[i * BT + t] = g_wpack[i * BT + t];

    unsigned long long acc[2][MIDP];
    #pragma unroll
    for (int rr = 0; rr < 2; ++rr)
        #pragma unroll
        for (int j = 0; j < MIDP; ++j) acc[rr][j] = 0ull;

    // thread's base pointer: row (row0+rgrp), column c
    const float* gthr = outputs + (size_t)(row0 + rgrp) * OUTP + c;

    #pragma unroll
    for (int ph = 0; ph < 2; ++ph) {
        // ---- stage 256x32 tile + in-register feature partials ----
        // Thread covers rows {rgrp + 4k} of each of the 8 sets in the block.
        // NOTE: r carries the full row offset; base pointer is NOT advanced.
        {
            const float* gs = gthr + ph * CH;
            float* xbase = &xs[c * XSTRIDE + rgrp];
            float* fbase = &fsh[rgrp * 256 + c];
            #pragma unroll
            for (int s = 0; s < 8; ++s) {              // 8 sets of 32 rows
                float f = 0.f;
                #pragma unroll
                for (int k = 0; k < 8; ++k) {
                    int r = s * 32 + k * 4;            // + rgrp implicit in pointers
                    float v = (row0 + r + rgrp < n_rows) ? gs[(size_t)r * OUTP] : 0.f;
                    xbase[r] = v;
                    f += v;
                }
                fbase[s * 32] = f;
            }
        }
        __syncthreads();

        // ---- fused {q,v} GEMV for rows t and t+128 ----
        #pragma unroll 8
        for (int cc = 0; cc < CH; ++cc) {
            float x0 = xs[cc * XSTRIDE + t];
            float x1 = xs[cc * XSTRIDE + t + 128];
            unsigned long long xp0 = pack2(x0, x0);
            unsigned long long xp1 = pack2(x1, x1);
            const ulonglong2* wr = (const ulonglong2*)&wsh[(ph * CH + cc) * MIDP];
            #pragma unroll
            for (int h = 0; h < 4; ++h) {
                ulonglong2 w = wr[h];
                ffma2(acc[0][h * 2 + 0], xp0, w.x);
                ffma2(acc[0][h * 2 + 1], xp0, w.y);
                ffma2(acc[1][h * 2 + 0], xp1, w.x);
                ffma2(acc[1][h * 2 + 1], xp1, w.y);
            }
        }

        // ---- feature outputs for this column phase (8 sets x 32 cols) ----
        #pragma unroll
        for (int p = 0; p < 2; ++p) {
            int pid = t + p * 128;                     // 0..255
            int s = pid >> 5, cc = pid & 31;
            float sum = fsh[s * 32 + cc] + fsh[256 + s * 32 + cc]
                      + fsh[512 + s * 32 + cc] + fsh[768 + s * 32 + cc];
            if (row0 + s * 32 < n_rows) {
                int srow = (row0 >> 5) + s;
                out[(size_t)srow * OUTP + ph * CH + cc] = sum;
            }
        }
        __syncthreads();
    }

    // ---- epilogue: positional correction, exp, vector scatter-reduce ----
    #pragma unroll
    for (int rr = 0; rr < 2; ++rr) {
        int row = row0 + t + rr * 128;
        if (row < n_rows) {
            float2 trv = translation[row];
            float r0 = fmaxf(psh[0] * trv.x + psh[1] * trv.y + psh[2], 0.f);
            float r1 = fmaxf(psh[3] * trv.x + psh[4] * trv.y + psh[5], 0.f);
            int sidx = indexes[row];
            float* seg = g_seg + (size_t)sidx * 16;
            float e[MIDP], ve[MIDP];
            #pragma unroll
            for (int j = 0; j < MIDP; ++j) {
                float q, v;
                unpack2(acc[rr][j], q, v);
                q += psh[6 + 2 * j] * r0 + psh[7 + 2 * j] * r1 + psh[22 + j];
                e[j]  = __expf(q);
                ve[j] = e[j] * (v + psh[30 + j]);
            }
            red4(seg +  0, e[0],  e[1],  e[2],  e[3]);
            red4(seg +  4, e[4],  e[5],  e[6],  e[7]);
            red4(seg +  8, ve[0], ve[1], ve[2], ve[3]);
            red4(seg + 12, ve[4], ve[5], ve[6], ve[7]);
        }
    }
}

// ---------- kernel 4: finalize (vectorized) ----------
__global__ void k_final(float4* __restrict__ out4, int total4) {
    int i = blockIdx.x * blockDim.x + threadIdx.x;
    if (i < total4) {
        int s  = i >> 4;                 // set (16 float4 per 64-wide row)
        int q4 = i & 15;
        int jb = (q4 & 1) * 4;           // column j-base (mod 8)
        const float4 e  = *(const float4*)&g_seg[(size_t)s * 16 + jb];
        const float4 ve = *(const float4*)&g_seg[(size_t)s * 16 + 8 + jb];
        float4 o = out4[i];
        o.x += (e.x > 0.f) ? ve.x / e.x : 0.f;
        o.y += (e.y > 0.f) ? ve.y / e.y : 0.f;
        o.z += (e.z > 0.f) ? ve.z / e.z : 0.f;
        o.w += (e.w > 0.f) ? ve.w / e.w : 0.f;
        out4[i] = o;
    }
}

// ---------- launcher ----------
extern "C" void kernel_launch(void* const* d_in, const int* in_sizes, int n_in,
                              void* d_out, int out_size) {
    const float* outputs     = (const float*)d_in[0];
    const float* translation = (const float*)d_in[1];
    const int*   indexes     = (const int*)d_in[2];
    const float* Wq  = (const float*)d_in[3];
    const float* bq  = (const float*)d_in[4];
    const float* Wv  = (const float*)d_in[5];
    const float* bv  = (const float*)d_in[6];
    const float* Wp1 = (const float*)d_in[7];
    const float* gma = (const float*)d_in[8];
    const float* bet = (const float*)d_in[9];
    const float* Wp2 = (const float*)d_in[10];
    const float* bp2 = (const float*)d_in[11];

    int n_rows = in_sizes[2];
    int n_sets = out_size / OUTP;
    if (n_sets > SEG_CAP) n_sets = SEG_CAP;

    void* segp = nullptr; void* momp = nullptr;
    cudaGetSymbolAddress(&segp, g_seg);
    cudaGetSymbolAddress(&momp, g_mom);
    cudaMemsetAsync(segp, 0, (size_t)n_sets * 16 * sizeof(float));
    cudaMemsetAsync(momp, 0, 5 * sizeof(double));

    k_moments<<<1024, 256>>>((const float2*)translation, n_rows);
    k_params<<<1, 128>>>(Wq, bq, Wv, bv, Wp1, gma, bet, Wp2, bp2, 1.0 / (double)n_rows);

    int nblocks = (n_rows + BR - 1) / BR;
    k_main<<<nblocks, BT>>>(outputs, (const float2*)translation, indexes, (float*)d_out, n_rows);

    int total4 = out_size / 4;
    k_final<<<(total4 + 255) / 256, 256>>>((float4*)d_out, total4);
}